// round 4
// baseline (speedup 1.0000x reference)
#include <cuda_runtime.h>
#include <cuda_bf16.h>
#include <cstdint>

#define C_DIM 64
#define H_DIM 12
#define HC 768            // H*C
#define MAXN 50048
#define MAXE 401024
#define NEG_SLOPE 0.2f
#define EPS_DEN 1e-16f

// ---------------- scratch (device globals: allocation-free rule) ----------------
__device__ float g_h[(size_t)MAXN * HC];      // projected features [N,H,C]
__device__ float g_asrc[MAXN * H_DIM];
__device__ float g_adst[MAXN * H_DIM];
__device__ int   g_deg[MAXN];
__device__ int   g_off[MAXN];                 // incl-scan temp, then exclusive offsets
__device__ int   g_cur[MAXN];
__device__ int   g_bsum[64];
__device__ int   g_ssrc[MAXE];                // edge src ids grouped by dst

// ---------------- helpers ----------------
__device__ __forceinline__ float lrelu(float v) {
    return v > 0.f ? v : NEG_SLOPE * v;
}
__device__ __forceinline__ unsigned fenc(float f) {
    unsigned u = __float_as_uint(f);
    return (u & 0x80000000u) ? ~u : (u | 0x80000000u);
}
__device__ __forceinline__ float fdec(unsigned e) {
    return (e & 0x80000000u) ? __uint_as_float(e & 0x7FFFFFFFu)
                             : __uint_as_float(~e);
}

// ---------------- K1: GEMM h = x @ W, fused a_src/a_dst epilogue ----------------
// grid = (H, ceil(N/64)), block = 256. Block (head, rowblk) computes h[rows, head, 0:64].
__global__ __launch_bounds__(256) void gemm_fused(
    const float* __restrict__ x, const float* __restrict__ W,
    const float* __restrict__ att_src, const float* __restrict__ att_dst, int N)
{
    __shared__ float As[64][65];
    __shared__ float Bs[64][65];
    __shared__ float att_s[64], att_d[64];
    __shared__ float red[64][17];

    const int head = blockIdx.x;
    const int row0 = blockIdx.y * 64;
    const int tid  = threadIdx.x;
    const int tx = tid & 15, ty = tid >> 4;

    if (tid < 64) {
        att_s[tid] = att_src[head * 64 + tid];
        att_d[tid] = att_dst[head * 64 + tid];
    }
    for (int i = tid; i < 64 * 64; i += 256) {
        int r = i >> 6, c = i & 63;
        int gr = row0 + r;
        As[r][c] = (gr < N) ? x[(size_t)gr * 64 + c] : 0.f;
        Bs[r][c] = W[r * HC + head * 64 + c];
    }
    __syncthreads();

    float acc[4][4] = {};
#pragma unroll
    for (int k = 0; k < 64; ++k) {
        float a[4], b[4];
#pragma unroll
        for (int r = 0; r < 4; ++r) a[r] = As[ty * 4 + r][k];
#pragma unroll
        for (int c = 0; c < 4; ++c) b[c] = Bs[k][tx * 4 + c];
#pragma unroll
        for (int r = 0; r < 4; ++r)
#pragma unroll
            for (int c = 0; c < 4; ++c) acc[r][c] = fmaf(a[r], b[c], acc[r][c]);
    }

    // store h (float4) + per-row partial dot products with att vectors
    float ps[4] = {}, pd[4] = {};
#pragma unroll
    for (int r = 0; r < 4; ++r) {
        int gr = row0 + ty * 4 + r;
#pragma unroll
        for (int c = 0; c < 4; ++c) {
            float v = acc[r][c];
            ps[r] = fmaf(v, att_s[tx * 4 + c], ps[r]);
            pd[r] = fmaf(v, att_d[tx * 4 + c], pd[r]);
        }
        if (gr < N) {
            float4 v4 = make_float4(acc[r][0], acc[r][1], acc[r][2], acc[r][3]);
            *reinterpret_cast<float4*>(&g_h[(size_t)gr * HC + head * 64 + tx * 4]) = v4;
        }
    }
    // reduce ps across tx (16 partials per row)
#pragma unroll
    for (int r = 0; r < 4; ++r) red[ty * 4 + r][tx] = ps[r];
    __syncthreads();
    if (tid < 64) {
        float s = 0.f;
#pragma unroll
        for (int j = 0; j < 16; ++j) s += red[tid][j];
        int gr = row0 + tid;
        if (gr < N) g_asrc[gr * H_DIM + head] = s;
    }
    __syncthreads();
#pragma unroll
    for (int r = 0; r < 4; ++r) red[ty * 4 + r][tx] = pd[r];
    __syncthreads();
    if (tid < 64) {
        float s = 0.f;
#pragma unroll
        for (int j = 0; j < 16; ++j) s += red[tid][j];
        int gr = row0 + tid;
        if (gr < N) g_adst[gr * H_DIM + head] = s;
    }
}

// ---------------- CSR build ----------------
__global__ void zero_deg(int N) {
    int i = blockIdx.x * blockDim.x + threadIdx.x;
    if (i < N) g_deg[i] = 0;
}
__global__ void hist_kernel(const int* __restrict__ dst, int E) {
    for (int e = blockIdx.x * blockDim.x + threadIdx.x; e < E;
         e += gridDim.x * blockDim.x)
        atomicAdd(&g_deg[dst[e]], 1);
}
__global__ __launch_bounds__(1024) void scan_block(int N) {
    __shared__ int sm[1024];
    int t = threadIdx.x;
    int i = blockIdx.x * 1024 + t;
    sm[t] = (i < N) ? g_deg[i] : 0;
    __syncthreads();
#pragma unroll
    for (int ofs = 1; ofs < 1024; ofs <<= 1) {
        int add = (t >= ofs) ? sm[t - ofs] : 0;
        __syncthreads();
        sm[t] += add;
        __syncthreads();
    }
    if (i < N) g_off[i] = sm[t];                 // inclusive (temp)
    if (t == 1023) g_bsum[blockIdx.x] = sm[1023];
}
__global__ __launch_bounds__(1024) void scan_bsum(int nb) {
    __shared__ int sm[1024];
    int t = threadIdx.x;
    int orig = (t < nb) ? g_bsum[t] : 0;
    sm[t] = orig;
    __syncthreads();
#pragma unroll
    for (int ofs = 1; ofs < 1024; ofs <<= 1) {
        int add = (t >= ofs) ? sm[t - ofs] : 0;
        __syncthreads();
        sm[t] += add;
        __syncthreads();
    }
    if (t < nb) g_bsum[t] = sm[t] - orig;        // exclusive block offsets
}
__global__ void finalize_off(int N) {
    int i = blockIdx.x * blockDim.x + threadIdx.x;
    if (i < N) {
        int ex = g_off[i] - g_deg[i] + g_bsum[i >> 10];
        g_off[i] = ex;
        g_cur[i] = ex;
    }
}
__global__ void scatter_kernel(const int* __restrict__ src, const int* __restrict__ dst, int E) {
    for (int e = blockIdx.x * blockDim.x + threadIdx.x; e < E;
         e += gridDim.x * blockDim.x) {
        int p = atomicAdd(&g_cur[dst[e]], 1);
        g_ssrc[p] = src[e];
    }
}

// ---------------- K6: per-node softmax + weighted aggregation ----------------
// one block (256 thr) per node; thread t owns feature indices {t, t+256, t+512} of [0,768)
__global__ __launch_bounds__(256) void aggregate(
    const float* __restrict__ x, const float* __restrict__ bias,
    float* __restrict__ out, int N)
{
    const int n = blockIdx.x;
    if (n >= N) return;
    const int t = threadIdx.x;

    __shared__ float    s_adst[H_DIM];
    __shared__ unsigned s_menc[H_DIM];
    __shared__ float    s_m[H_DIM];
    __shared__ float    s_sum[H_DIM];
    __shared__ float    s_wself[H_DIM];
    __shared__ float    s_w[64 * H_DIM];
    __shared__ int      s_src[64];
    __shared__ float    s_part[256];

    const int dg = g_deg[n];
    const int o  = g_off[n];

    if (t < H_DIM) { s_adst[t] = g_adst[n * H_DIM + t]; s_menc[t] = 0u; }
    __syncthreads();

    // ---- pass 1: per-head max (self loop + edges) ----
    if (t < H_DIM) {
        float al = lrelu(g_asrc[n * H_DIM + t] + s_adst[t]);
        atomicMax(&s_menc[t], fenc(al));
    }
    for (int base = 0; base < dg; base += 64) {
        int cnt = min(64, dg - base);
        if (t < cnt) s_src[t] = g_ssrc[o + base + t];
        __syncthreads();
        for (int idx = t; idx < cnt * H_DIM; idx += 256) {
            int e = idx / H_DIM, hh = idx - e * H_DIM;
            float al = lrelu(g_asrc[s_src[e] * H_DIM + hh] + s_adst[hh]);
            atomicMax(&s_menc[hh], fenc(al));
        }
        __syncthreads();
    }
    if (t < H_DIM) { s_m[t] = fdec(s_menc[t]); s_sum[t] = 0.f; }
    __syncthreads();

    // ---- pass 2: exp-sum + weighted feature accumulation ----
    float acc0, acc1, acc2;
    if (t < H_DIM) {
        float al = lrelu(g_asrc[n * H_DIM + t] + s_adst[t]);
        float w = __expf(al - s_m[t]);
        s_wself[t] = w;
        s_sum[t] += w;          // exclusive per-thread slot
    }
    __syncthreads();
    {
        const float* hp = g_h + (size_t)n * HC;
        acc0 = s_wself[t >> 6]         * hp[t];
        acc1 = s_wself[(t + 256) >> 6] * hp[t + 256];
        acc2 = s_wself[(t + 512) >> 6] * hp[t + 512];
    }
    for (int base = 0; base < dg; base += 64) {
        int cnt = min(64, dg - base);
        if (t < cnt) s_src[t] = g_ssrc[o + base + t];
        __syncthreads();
        for (int idx = t; idx < cnt * H_DIM; idx += 256) {
            int e = idx / H_DIM, hh = idx - e * H_DIM;
            float al = lrelu(g_asrc[s_src[e] * H_DIM + hh] + s_adst[hh]);
            float w = __expf(al - s_m[hh]);
            s_w[idx] = w;
            atomicAdd(&s_sum[hh], w);
        }
        __syncthreads();
        for (int e = 0; e < cnt; ++e) {
            const float* hp = g_h + (size_t)s_src[e] * HC;
            float w0 = s_w[e * H_DIM + (t >> 6)];
            float w1 = s_w[e * H_DIM + ((t + 256) >> 6)];
            float w2 = s_w[e * H_DIM + ((t + 512) >> 6)];
            acc0 = fmaf(w0, hp[t],       acc0);
            acc1 = fmaf(w1, hp[t + 256], acc1);
            acc2 = fmaf(w2, hp[t + 512], acc2);
        }
        __syncthreads();
    }

    // ---- normalize per head, partial head-mean ----
    float p = acc0 / (s_sum[t >> 6] + EPS_DEN)
            + acc1 / (s_sum[(t + 256) >> 6] + EPS_DEN)
            + acc2 / (s_sum[(t + 512) >> 6] + EPS_DEN);
    s_part[t] = p;
    __syncthreads();
    if (t < 64) {
        float v = s_part[t] + s_part[t + 64] + s_part[t + 128] + s_part[t + 192];
        v = v * (1.f / (float)H_DIM) + bias[t] + x[(size_t)n * 64 + t];
        out[(size_t)n * 64 + t] = fmaxf(v, 0.f);
    }
}

// ---------------- launch ----------------
extern "C" void kernel_launch(void* const* d_in, const int* in_sizes, int n_in,
                              void* d_out, int out_size)
{
    (void)n_in; (void)out_size;
    const float* x     = (const float*)d_in[0];
    const int*   ei    = (const int*)  d_in[1];
    const float* W     = (const float*)d_in[2];
    const float* att_s = (const float*)d_in[3];
    const float* att_d = (const float*)d_in[4];
    const float* bias  = (const float*)d_in[5];
    float* out = (float*)d_out;

    const int N = in_sizes[0] / C_DIM;
    const int E = in_sizes[1] / 2;
    const int* src = ei;
    const int* dst = ei + E;

    gemm_fused<<<dim3(H_DIM, (N + 63) / 64), 256>>>(x, W, att_s, att_d, N);

    zero_deg<<<(N + 255) / 256, 256>>>(N);
    hist_kernel<<<592, 256>>>(dst, E);
    int nb = (N + 1023) / 1024;
    scan_block<<<nb, 1024>>>(N);
    scan_bsum<<<1, 1024>>>(nb);
    finalize_off<<<(N + 255) / 256, 256>>>(N);
    scatter_kernel<<<592, 256>>>(src, dst, E);

    aggregate<<<N, 256>>>(x, bias, out, N);
}

// round 6
// speedup vs baseline: 1.0491x; 1.0491x over previous
#include <cuda_runtime.h>
#include <cuda_bf16.h>
#include <cstdint>

#define C_DIM 64
#define H_DIM 12
#define HC 768            // H*C
#define MAXN 50048
#define MAXE 401024
#define NEG_SLOPE 0.2f
#define EPS_DEN 1e-16f

// ---------------- scratch (device globals: allocation-free rule) ----------------
__device__ float g_h[(size_t)MAXN * HC];      // projected features [N,H,C]
__device__ float g_asrc[MAXN * H_DIM];
__device__ float g_adst[MAXN * H_DIM];
__device__ int   g_deg[MAXN];
__device__ int   g_off[MAXN];                 // incl-scan temp, then exclusive offsets
__device__ int   g_cur[MAXN];
__device__ int   g_bsum[64];
__device__ int   g_ssrc[MAXE];                // edge src ids grouped by dst

// ---------------- helpers ----------------
__device__ __forceinline__ float lrelu(float v) {
    return v > 0.f ? v : NEG_SLOPE * v;
}
__device__ __forceinline__ unsigned fenc(float f) {
    unsigned u = __float_as_uint(f);
    return (u & 0x80000000u) ? ~u : (u | 0x80000000u);
}
__device__ __forceinline__ float fdec(unsigned e) {
    return (e & 0x80000000u) ? __uint_as_float(e & 0x7FFFFFFFu)
                             : __uint_as_float(~e);
}

// ---------------- K1: GEMM h = x @ W, fused a_src/a_dst epilogue ----------------
// grid = (H, ceil(N/64)), block = 256. Block (head, rowblk) computes h[rows, head, 0:64].
// A tile stored transposed (Ast[k][row]) so the inner loop is 2x LDS.128 + 16 FFMA.
__global__ __launch_bounds__(256) void gemm_fused(
    const float* __restrict__ x, const float* __restrict__ W,
    const float* __restrict__ att_src, const float* __restrict__ att_dst, int N)
{
    __shared__ float Ast[64][68];   // [k][row], 68-pad: 16B-aligned rows
    __shared__ float Bs[64][68];    // [k][col]
    __shared__ float att_s[64], att_d[64];
    __shared__ float red[64][17];

    const int head = blockIdx.x;
    const int row0 = blockIdx.y * 64;
    const int tid  = threadIdx.x;
    const int tx = tid & 15, ty = tid >> 4;

    if (tid < 64) {
        att_s[tid] = att_src[head * 64 + tid];
        att_d[tid] = att_dst[head * 64 + tid];
    }
    for (int i = tid; i < 64 * 64; i += 256) {
        int r = i >> 6, c = i & 63;
        int gr = row0 + r;
        Ast[c][r] = (gr < N) ? x[(size_t)gr * 64 + c] : 0.f;
        Bs[r][c]  = W[r * HC + head * 64 + c];
    }
    __syncthreads();

    float acc[4][4] = {};
#pragma unroll
    for (int k = 0; k < 64; ++k) {
        float4 a4 = *reinterpret_cast<const float4*>(&Ast[k][ty * 4]);
        float4 b4 = *reinterpret_cast<const float4*>(&Bs[k][tx * 4]);
        float a[4] = {a4.x, a4.y, a4.z, a4.w};
        float b[4] = {b4.x, b4.y, b4.z, b4.w};
#pragma unroll
        for (int r = 0; r < 4; ++r)
#pragma unroll
            for (int c = 0; c < 4; ++c) acc[r][c] = fmaf(a[r], b[c], acc[r][c]);
    }

    // store h (float4) + per-row partial dot products with att vectors
    float ps[4] = {}, pd[4] = {};
#pragma unroll
    for (int r = 0; r < 4; ++r) {
        int gr = row0 + ty * 4 + r;
#pragma unroll
        for (int c = 0; c < 4; ++c) {
            float v = acc[r][c];
            ps[r] = fmaf(v, att_s[tx * 4 + c], ps[r]);
            pd[r] = fmaf(v, att_d[tx * 4 + c], pd[r]);
        }
        if (gr < N) {
            float4 v4 = make_float4(acc[r][0], acc[r][1], acc[r][2], acc[r][3]);
            *reinterpret_cast<float4*>(&g_h[(size_t)gr * HC + head * 64 + tx * 4]) = v4;
        }
    }
    // reduce ps across tx (16 partials per row)
#pragma unroll
    for (int r = 0; r < 4; ++r) red[ty * 4 + r][tx] = ps[r];
    __syncthreads();
    if (tid < 64) {
        float s = 0.f;
#pragma unroll
        for (int j = 0; j < 16; ++j) s += red[tid][j];
        int gr = row0 + tid;
        if (gr < N) g_asrc[gr * H_DIM + head] = s;
    }
    __syncthreads();
#pragma unroll
    for (int r = 0; r < 4; ++r) red[ty * 4 + r][tx] = pd[r];
    __syncthreads();
    if (tid < 64) {
        float s = 0.f;
#pragma unroll
        for (int j = 0; j < 16; ++j) s += red[tid][j];
        int gr = row0 + tid;
        if (gr < N) g_adst[gr * H_DIM + head] = s;
    }
}

// ---------------- CSR build ----------------
__global__ void zero_deg(int N) {
    int i = blockIdx.x * blockDim.x + threadIdx.x;
    if (i < N) g_deg[i] = 0;
}
__global__ void hist_kernel(const int* __restrict__ dst, int E) {
    for (int e = blockIdx.x * blockDim.x + threadIdx.x; e < E;
         e += gridDim.x * blockDim.x)
        atomicAdd(&g_deg[dst[e]], 1);
}
__global__ __launch_bounds__(1024) void scan_block(int N) {
    __shared__ int sm[1024];
    int t = threadIdx.x;
    int i = blockIdx.x * 1024 + t;
    sm[t] = (i < N) ? g_deg[i] : 0;
    __syncthreads();
#pragma unroll
    for (int ofs = 1; ofs < 1024; ofs <<= 1) {
        int add = (t >= ofs) ? sm[t - ofs] : 0;
        __syncthreads();
        sm[t] += add;
        __syncthreads();
    }
    if (i < N) g_off[i] = sm[t];                 // inclusive (temp)
    if (t == 1023) g_bsum[blockIdx.x] = sm[1023];
}
__global__ __launch_bounds__(1024) void scan_bsum(int nb) {
    __shared__ int sm[1024];
    int t = threadIdx.x;
    int orig = (t < nb) ? g_bsum[t] : 0;
    sm[t] = orig;
    __syncthreads();
#pragma unroll
    for (int ofs = 1; ofs < 1024; ofs <<= 1) {
        int add = (t >= ofs) ? sm[t - ofs] : 0;
        __syncthreads();
        sm[t] += add;
        __syncthreads();
    }
    if (t < nb) g_bsum[t] = sm[t] - orig;        // exclusive block offsets
}
__global__ void finalize_off(int N) {
    int i = blockIdx.x * blockDim.x + threadIdx.x;
    if (i < N) {
        int ex = g_off[i] - g_deg[i] + g_bsum[i >> 10];
        g_off[i] = ex;
        g_cur[i] = ex;
    }
}
__global__ void scatter_kernel(const int* __restrict__ src, const int* __restrict__ dst, int E) {
    for (int e = blockIdx.x * blockDim.x + threadIdx.x; e < E;
         e += gridDim.x * blockDim.x) {
        int p = atomicAdd(&g_cur[dst[e]], 1);
        g_ssrc[p] = src[e];
    }
}

// ---------------- K6: per-node softmax + weighted aggregation ----------------
// one block (192 thr) per node; thread t owns float4 feature chunk [4t, 4t+4)
// of the 768-wide h row; head of chunk t is t>>4 (16 float4 per 64-wide head).
__global__ __launch_bounds__(192) void aggregate(
    const float* __restrict__ x, const float* __restrict__ bias,
    float* __restrict__ out, int N)
{
    const int n = blockIdx.x;
    const int t = threadIdx.x;
    const int head = t >> 4;

    __shared__ float    s_adst[H_DIM];
    __shared__ unsigned s_menc[H_DIM];
    __shared__ float    s_m[H_DIM];
    __shared__ float    s_sum[H_DIM];
    __shared__ float    s_w[64 * H_DIM];
    __shared__ int      s_src[64];
    __shared__ float    s_feat[HC];

    const int dg = g_deg[n];
    const int o  = g_off[n];

    if (t < H_DIM) { s_adst[t] = g_adst[n * H_DIM + t]; s_menc[t] = 0u; }
    __syncthreads();

    // ---- pass 1: per-head max (self loop + edges) ----
    if (t < H_DIM) {
        float al = lrelu(g_asrc[n * H_DIM + t] + s_adst[t]);
        atomicMax(&s_menc[t], fenc(al));
    }
    for (int base = 0; base < dg; base += 64) {
        int cnt = min(64, dg - base);
        if (t < cnt) s_src[t] = g_ssrc[o + base + t];
        __syncthreads();
        for (int idx = t; idx < cnt * H_DIM; idx += 192) {
            int e = idx / H_DIM, hh = idx - e * H_DIM;
            float al = lrelu(g_asrc[s_src[e] * H_DIM + hh] + s_adst[hh]);
            atomicMax(&s_menc[hh], fenc(al));
        }
        __syncthreads();
    }
    if (t < H_DIM) { s_m[t] = fdec(s_menc[t]); s_sum[t] = 0.f; }
    __syncthreads();

    // ---- self-loop contribution ----
    if (t < H_DIM) {
        float al = lrelu(g_asrc[n * H_DIM + t] + s_adst[t]);
        float w = __expf(al - s_m[t]);
        s_w[t]   = w;        // temp: self weights in s_w[0..11]
        s_sum[t] = w;
    }
    __syncthreads();
    float4 acc;
    {
        float w = s_w[head];
        float4 hv = *reinterpret_cast<const float4*>(g_h + (size_t)n * HC + t * 4);
        acc.x = w * hv.x; acc.y = w * hv.y; acc.z = w * hv.z; acc.w = w * hv.w;
    }
    __syncthreads();

    // ---- pass 2: exp-sum + weighted feature accumulation (64-edge chunks) ----
    for (int base = 0; base < dg; base += 64) {
        int cnt = min(64, dg - base);
        if (t < cnt) s_src[t] = g_ssrc[o + base + t];
        __syncthreads();
        for (int idx = t; idx < cnt * H_DIM; idx += 192) {
            int e = idx / H_DIM, hh = idx - e * H_DIM;
            float al = lrelu(g_asrc[s_src[e] * H_DIM + hh] + s_adst[hh]);
            float w = __expf(al - s_m[hh]);
            s_w[idx] = w;
            atomicAdd(&s_sum[hh], w);
        }
        __syncthreads();

        int e = 0;
        for (; e + 4 <= cnt; e += 4) {
            const float4 h0 = *reinterpret_cast<const float4*>(g_h + (size_t)s_src[e]     * HC + t * 4);
            const float4 h1 = *reinterpret_cast<const float4*>(g_h + (size_t)s_src[e + 1] * HC + t * 4);
            const float4 h2 = *reinterpret_cast<const float4*>(g_h + (size_t)s_src[e + 2] * HC + t * 4);
            const float4 h3 = *reinterpret_cast<const float4*>(g_h + (size_t)s_src[e + 3] * HC + t * 4);
            float w0 = s_w[(e)     * H_DIM + head];
            float w1 = s_w[(e + 1) * H_DIM + head];
            float w2 = s_w[(e + 2) * H_DIM + head];
            float w3 = s_w[(e + 3) * H_DIM + head];
            acc.x = fmaf(w0, h0.x, acc.x); acc.y = fmaf(w0, h0.y, acc.y);
            acc.z = fmaf(w0, h0.z, acc.z); acc.w = fmaf(w0, h0.w, acc.w);
            acc.x = fmaf(w1, h1.x, acc.x); acc.y = fmaf(w1, h1.y, acc.y);
            acc.z = fmaf(w1, h1.z, acc.z); acc.w = fmaf(w1, h1.w, acc.w);
            acc.x = fmaf(w2, h2.x, acc.x); acc.y = fmaf(w2, h2.y, acc.y);
            acc.z = fmaf(w2, h2.z, acc.z); acc.w = fmaf(w2, h2.w, acc.w);
            acc.x = fmaf(w3, h3.x, acc.x); acc.y = fmaf(w3, h3.y, acc.y);
            acc.z = fmaf(w3, h3.z, acc.z); acc.w = fmaf(w3, h3.w, acc.w);
        }
        for (; e < cnt; ++e) {
            const float4 hv = *reinterpret_cast<const float4*>(g_h + (size_t)s_src[e] * HC + t * 4);
            float w = s_w[e * H_DIM + head];
            acc.x = fmaf(w, hv.x, acc.x); acc.y = fmaf(w, hv.y, acc.y);
            acc.z = fmaf(w, hv.z, acc.z); acc.w = fmaf(w, hv.w, acc.w);
        }
        __syncthreads();
    }

    // ---- normalize per head, head-mean, residual, relu ----
    {
        float inv = 1.f / (s_sum[head] + EPS_DEN);
        float4 v = make_float4(acc.x * inv, acc.y * inv, acc.z * inv, acc.w * inv);
        *reinterpret_cast<float4*>(&s_feat[t * 4]) = v;
    }
    __syncthreads();
    if (t < 64) {
        float v = 0.f;
#pragma unroll
        for (int h = 0; h < H_DIM; ++h) v += s_feat[h * 64 + t];
        v = v * (1.f / (float)H_DIM) + bias[t] + x[(size_t)n * 64 + t];
        out[(size_t)n * 64 + t] = fmaxf(v, 0.f);
    }
}

// ---------------- launch ----------------
extern "C" void kernel_launch(void* const* d_in, const int* in_sizes, int n_in,
                              void* d_out, int out_size)
{
    (void)n_in; (void)out_size;
    const float* x     = (const float*)d_in[0];
    const int*   ei    = (const int*)  d_in[1];
    const float* W     = (const float*)d_in[2];
    const float* att_s = (const float*)d_in[3];
    const float* att_d = (const float*)d_in[4];
    const float* bias  = (const float*)d_in[5];
    float* out = (float*)d_out;

    const int N = in_sizes[0] / C_DIM;
    const int E = in_sizes[1] / 2;
    const int* src = ei;
    const int* dst = ei + E;

    gemm_fused<<<dim3(H_DIM, (N + 63) / 64), 256>>>(x, W, att_s, att_d, N);

    zero_deg<<<(N + 255) / 256, 256>>>(N);
    hist_kernel<<<592, 256>>>(dst, E);
    int nb = (N + 1023) / 1024;
    scan_block<<<nb, 1024>>>(N);
    scan_bsum<<<1, 1024>>>(nb);
    finalize_off<<<(N + 255) / 256, 256>>>(N);
    scatter_kernel<<<592, 256>>>(src, dst, E);

    aggregate<<<N, 192>>>(x, bias, out, N);
}

// round 11
// speedup vs baseline: 1.4048x; 1.3392x over previous
#include <cuda_runtime.h>
#include <cuda_fp16.h>
#include <cstdint>

#define C_DIM 64
#define H_DIM 12
#define HC 768            // H*C
#define MAXN 50048
#define MAXE 401024
#define NEG_SLOPE 0.2f
#define EPS_DEN 1e-16f

// ---------------- scratch (device globals: allocation-free rule) ----------------
__device__ __half g_hh[(size_t)MAXN * HC];    // projected features [N,H,C] in fp16 (77MB: fits L2)
__device__ float g_asrc[MAXN * H_DIM];
__device__ float g_adst[MAXN * H_DIM];
__device__ int   g_deg[MAXN];
__device__ int   g_off[MAXN];                 // incl-scan temp, then exclusive offsets
__device__ int   g_cur[MAXN];
__device__ int   g_bsum[64];
__device__ int   g_ssrc[MAXE];                // edge src ids grouped by dst

// ---------------- helpers ----------------
__device__ __forceinline__ float lrelu(float v) {
    return v > 0.f ? v : NEG_SLOPE * v;
}
__device__ __forceinline__ unsigned fenc(float f) {
    unsigned u = __float_as_uint(f);
    return (u & 0x80000000u) ? ~u : (u | 0x80000000u);
}
__device__ __forceinline__ float fdec(unsigned e) {
    return (e & 0x80000000u) ? __uint_as_float(e & 0x7FFFFFFFu)
                             : __uint_as_float(~e);
}

// ---------------- K1: GEMM h = x @ W, fused a_src/a_dst epilogue ----------------
// grid = (H, ceil(N/64)), block = 256. Block (head, rowblk) computes h[rows, head, 0:64].
// Attention logits computed from fp32 accumulators; h stored as fp16.
__global__ __launch_bounds__(256) void gemm_fused(
    const float* __restrict__ x, const float* __restrict__ W,
    const float* __restrict__ att_src, const float* __restrict__ att_dst, int N)
{
    __shared__ float Ast[64][68];   // [k][row], 68-pad: 16B-aligned rows
    __shared__ float Bs[64][68];    // [k][col]
    __shared__ float att_s[64], att_d[64];
    __shared__ float red[64][17];

    const int head = blockIdx.x;
    const int row0 = blockIdx.y * 64;
    const int tid  = threadIdx.x;
    const int tx = tid & 15, ty = tid >> 4;

    if (tid < 64) {
        att_s[tid] = att_src[head * 64 + tid];
        att_d[tid] = att_dst[head * 64 + tid];
    }
    for (int i = tid; i < 64 * 64; i += 256) {
        int r = i >> 6, c = i & 63;
        int gr = row0 + r;
        Ast[c][r] = (gr < N) ? x[(size_t)gr * 64 + c] : 0.f;
        Bs[r][c]  = W[r * HC + head * 64 + c];
    }
    __syncthreads();

    float acc[4][4] = {};
#pragma unroll
    for (int k = 0; k < 64; ++k) {
        float4 a4 = *reinterpret_cast<const float4*>(&Ast[k][ty * 4]);
        float4 b4 = *reinterpret_cast<const float4*>(&Bs[k][tx * 4]);
        float a[4] = {a4.x, a4.y, a4.z, a4.w};
        float b[4] = {b4.x, b4.y, b4.z, b4.w};
#pragma unroll
        for (int r = 0; r < 4; ++r)
#pragma unroll
            for (int c = 0; c < 4; ++c) acc[r][c] = fmaf(a[r], b[c], acc[r][c]);
    }

    // store h (2x half2 = 8B) + per-row partial dot products with att vectors (fp32)
    float ps[4] = {}, pd[4] = {};
#pragma unroll
    for (int r = 0; r < 4; ++r) {
        int gr = row0 + ty * 4 + r;
#pragma unroll
        for (int c = 0; c < 4; ++c) {
            float v = acc[r][c];
            ps[r] = fmaf(v, att_s[tx * 4 + c], ps[r]);
            pd[r] = fmaf(v, att_d[tx * 4 + c], pd[r]);
        }
        if (gr < N) {
            __half2 p0 = __floats2half2_rn(acc[r][0], acc[r][1]);
            __half2 p1 = __floats2half2_rn(acc[r][2], acc[r][3]);
            __half2* hp = reinterpret_cast<__half2*>(
                g_hh + (size_t)gr * HC + head * 64 + tx * 4);
            hp[0] = p0;
            hp[1] = p1;
        }
    }
    // reduce ps across tx (16 partials per row)
#pragma unroll
    for (int r = 0; r < 4; ++r) red[ty * 4 + r][tx] = ps[r];
    __syncthreads();
    if (tid < 64) {
        float s = 0.f;
#pragma unroll
        for (int j = 0; j < 16; ++j) s += red[tid][j];
        int gr = row0 + tid;
        if (gr < N) g_asrc[gr * H_DIM + head] = s;
    }
    __syncthreads();
#pragma unroll
    for (int r = 0; r < 4; ++r) red[ty * 4 + r][tx] = pd[r];
    __syncthreads();
    if (tid < 64) {
        float s = 0.f;
#pragma unroll
        for (int j = 0; j < 16; ++j) s += red[tid][j];
        int gr = row0 + tid;
        if (gr < N) g_adst[gr * H_DIM + head] = s;
    }
}

// ---------------- CSR build ----------------
__global__ void zero_deg(int N) {
    int i = blockIdx.x * blockDim.x + threadIdx.x;
    if (i < N) g_deg[i] = 0;
}
__global__ void hist_kernel(const int* __restrict__ dst, int E) {
    for (int e = blockIdx.x * blockDim.x + threadIdx.x; e < E;
         e += gridDim.x * blockDim.x)
        atomicAdd(&g_deg[dst[e]], 1);
}
__global__ __launch_bounds__(1024) void scan_block(int N) {
    __shared__ int sm[1024];
    int t = threadIdx.x;
    int i = blockIdx.x * 1024 + t;
    sm[t] = (i < N) ? g_deg[i] : 0;
    __syncthreads();
#pragma unroll
    for (int ofs = 1; ofs < 1024; ofs <<= 1) {
        int add = (t >= ofs) ? sm[t - ofs] : 0;
        __syncthreads();
        sm[t] += add;
        __syncthreads();
    }
    if (i < N) g_off[i] = sm[t];                 // inclusive (temp)
    if (t == 1023) g_bsum[blockIdx.x] = sm[1023];
}
__global__ __launch_bounds__(1024) void scan_bsum(int nb) {
    __shared__ int sm[1024];
    int t = threadIdx.x;
    int orig = (t < nb) ? g_bsum[t] : 0;
    sm[t] = orig;
    __syncthreads();
#pragma unroll
    for (int ofs = 1; ofs < 1024; ofs <<= 1) {
        int add = (t >= ofs) ? sm[t - ofs] : 0;
        __syncthreads();
        sm[t] += add;
        __syncthreads();
    }
    if (t < nb) g_bsum[t] = sm[t] - orig;        // exclusive block offsets
}
__global__ void finalize_off(int N) {
    int i = blockIdx.x * blockDim.x + threadIdx.x;
    if (i < N) {
        int ex = g_off[i] - g_deg[i] + g_bsum[i >> 10];
        g_off[i] = ex;
        g_cur[i] = ex;
    }
}
__global__ void scatter_kernel(const int* __restrict__ src, const int* __restrict__ dst, int E) {
    for (int e = blockIdx.x * blockDim.x + threadIdx.x; e < E;
         e += gridDim.x * blockDim.x) {
        int p = atomicAdd(&g_cur[dst[e]], 1);
        g_ssrc[p] = src[e];
    }
}

// ---------------- K6: per-node softmax + weighted aggregation ----------------
// one block (192 thr) per node; thread t owns features [4t, 4t+4) of the 768-wide
// h row (one LDG.64 = 2x half2 per edge); head of thread t is t>>4.
__global__ __launch_bounds__(192) void aggregate(
    const float* __restrict__ x, const float* __restrict__ bias,
    float* __restrict__ out, int N)
{
    const int n = blockIdx.x;
    const int t = threadIdx.x;
    const int head = t >> 4;

    __shared__ float    s_adst[H_DIM];
    __shared__ unsigned s_menc[H_DIM];
    __shared__ float    s_m[H_DIM];
    __shared__ float    s_sum[H_DIM];
    __shared__ float    s_w[64 * H_DIM];
    __shared__ int      s_src[64];
    __shared__ float    s_feat[HC];

    const int dg = g_deg[n];
    const int o  = g_off[n];

    if (t < H_DIM) { s_adst[t] = g_adst[n * H_DIM + t]; s_menc[t] = 0u; }
    __syncthreads();

    // ---- pass 1: per-head max (self loop + edges) ----
    if (t < H_DIM) {
        float al = lrelu(g_asrc[n * H_DIM + t] + s_adst[t]);
        atomicMax(&s_menc[t], fenc(al));
    }
    for (int base = 0; base < dg; base += 64) {
        int cnt = min(64, dg - base);
        if (t < cnt) s_src[t] = g_ssrc[o + base + t];
        __syncthreads();
        for (int idx = t; idx < cnt * H_DIM; idx += 192) {
            int e = idx / H_DIM, hh = idx - e * H_DIM;
            float al = lrelu(g_asrc[s_src[e] * H_DIM + hh] + s_adst[hh]);
            atomicMax(&s_menc[hh], fenc(al));
        }
        __syncthreads();
    }
    if (t < H_DIM) { s_m[t] = fdec(s_menc[t]); s_sum[t] = 0.f; }
    __syncthreads();

    // ---- self-loop contribution ----
    if (t < H_DIM) {
        float al = lrelu(g_asrc[n * H_DIM + t] + s_adst[t]);
        float w = __expf(al - s_m[t]);
        s_w[t]   = w;        // temp: self weights in s_w[0..11]
        s_sum[t] = w;
    }
    __syncthreads();
    float a0, a1, a2, a3;
    {
        float w = s_w[head];
        const __half2* hp = reinterpret_cast<const __half2*>(g_hh + (size_t)n * HC + t * 4);
        float2 f0 = __half22float2(hp[0]);
        float2 f1 = __half22float2(hp[1]);
        a0 = w * f0.x; a1 = w * f0.y; a2 = w * f1.x; a3 = w * f1.y;
    }
    __syncthreads();

    // ---- pass 2: exp-sum + weighted feature accumulation (64-edge chunks) ----
    for (int base = 0; base < dg; base += 64) {
        int cnt = min(64, dg - base);
        if (t < cnt) s_src[t] = g_ssrc[o + base + t];
        __syncthreads();
        for (int idx = t; idx < cnt * H_DIM; idx += 192) {
            int e = idx / H_DIM, hh = idx - e * H_DIM;
            float al = lrelu(g_asrc[s_src[e] * H_DIM + hh] + s_adst[hh]);
            float w = __expf(al - s_m[hh]);
            s_w[idx] = w;
            atomicAdd(&s_sum[hh], w);
        }
        __syncthreads();

        int e = 0;
        for (; e + 4 <= cnt; e += 4) {
            const __half2* p0 = reinterpret_cast<const __half2*>(g_hh + (size_t)s_src[e]     * HC + t * 4);
            const __half2* p1 = reinterpret_cast<const __half2*>(g_hh + (size_t)s_src[e + 1] * HC + t * 4);
            const __half2* p2 = reinterpret_cast<const __half2*>(g_hh + (size_t)s_src[e + 2] * HC + t * 4);
            const __half2* p3 = reinterpret_cast<const __half2*>(g_hh + (size_t)s_src[e + 3] * HC + t * 4);
            __half2 h0a = p0[0], h0b = p0[1];
            __half2 h1a = p1[0], h1b = p1[1];
            __half2 h2a = p2[0], h2b = p2[1];
            __half2 h3a = p3[0], h3b = p3[1];
            float w0 = s_w[(e)     * H_DIM + head];
            float w1 = s_w[(e + 1) * H_DIM + head];
            float w2 = s_w[(e + 2) * H_DIM + head];
            float w3 = s_w[(e + 3) * H_DIM + head];
            float2 f;
            f = __half22float2(h0a); a0 = fmaf(w0, f.x, a0); a1 = fmaf(w0, f.y, a1);
            f = __half22float2(h0b); a2 = fmaf(w0, f.x, a2); a3 = fmaf(w0, f.y, a3);
            f = __half22float2(h1a); a0 = fmaf(w1, f.x, a0); a1 = fmaf(w1, f.y, a1);
            f = __half22float2(h1b); a2 = fmaf(w1, f.x, a2); a3 = fmaf(w1, f.y, a3);
            f = __half22float2(h2a); a0 = fmaf(w2, f.x, a0); a1 = fmaf(w2, f.y, a1);
            f = __half22float2(h2b); a2 = fmaf(w2, f.x, a2); a3 = fmaf(w2, f.y, a3);
            f = __half22float2(h3a); a0 = fmaf(w3, f.x, a0); a1 = fmaf(w3, f.y, a1);
            f = __half22float2(h3b); a2 = fmaf(w3, f.x, a2); a3 = fmaf(w3, f.y, a3);
        }
        for (; e < cnt; ++e) {
            const __half2* p = reinterpret_cast<const __half2*>(g_hh + (size_t)s_src[e] * HC + t * 4);
            __half2 ha = p[0], hb = p[1];
            float w = s_w[e * H_DIM + head];
            float2 f;
            f = __half22float2(ha); a0 = fmaf(w, f.x, a0); a1 = fmaf(w, f.y, a1);
            f = __half22float2(hb); a2 = fmaf(w, f.x, a2); a3 = fmaf(w, f.y, a3);
        }
        __syncthreads();
    }

    // ---- normalize per head, head-mean, residual, relu ----
    {
        float inv = 1.f / (s_sum[head] + EPS_DEN);
        float4 v = make_float4(a0 * inv, a1 * inv, a2 * inv, a3 * inv);
        *reinterpret_cast<float4*>(&s_feat[t * 4]) = v;
    }
    __syncthreads();
    if (t < 64) {
        float v = 0.f;
#pragma unroll
        for (int h = 0; h < H_DIM; ++h) v += s_feat[h * 64 + t];
        v = v * (1.f / (float)H_DIM) + bias[t] + x[(size_t)n * 64 + t];
        out[(size_t)n * 64 + t] = fmaxf(v, 0.f);
    }
}

// ---------------- launch ----------------
extern "C" void kernel_launch(void* const* d_in, const int* in_sizes, int n_in,
                              void* d_out, int out_size)
{
    (void)n_in; (void)out_size;
    const float* x     = (const float*)d_in[0];
    const int*   ei    = (const int*)  d_in[1];
    const float* W     = (const float*)d_in[2];
    const float* att_s = (const float*)d_in[3];
    const float* att_d = (const float*)d_in[4];
    const float* bias  = (const float*)d_in[5];
    float* out = (float*)d_out;

    const int N = in_sizes[0] / C_DIM;
    const int E = in_sizes[1] / 2;
    const int* src = ei;
    const int* dst = ei + E;

    // CSR chain and GEMM are independent; GEMM placed 4th so the ncu capture
    // (which empirically lands on the 4th launch) profiles it.
    zero_deg<<<(N + 255) / 256, 256>>>(N);
    hist_kernel<<<592, 256>>>(dst, E);
    int nb = (N + 1023) / 1024;
    scan_block<<<nb, 1024>>>(N);

    gemm_fused<<<dim3(H_DIM, (N + 63) / 64), 256>>>(x, W, att_s, att_d, N);

    scan_bsum<<<1, 1024>>>(nb);
    finalize_off<<<(N + 255) / 256, 256>>>(N);
    scatter_kernel<<<592, 256>>>(src, dst, E);

    aggregate<<<N, 192>>>(x, bias, out, N);
}

// round 14
// speedup vs baseline: 1.8985x; 1.3514x over previous
#include <cuda_runtime.h>
#include <cuda_fp16.h>
#include <mma.h>
#include <cstdint>

using namespace nvcuda;

#define C_DIM 64
#define H_DIM 12
#define HC 768            // H*C
#define MAXN 50048
#define MAXE 401024
#define NEG_SLOPE 0.2f
#define EPS_DEN 1e-16f

// ---------------- scratch (device globals: allocation-free rule) ----------------
__device__ __half g_hh[(size_t)MAXN * HC];    // projected features [N,H,C] fp16 (77MB: fits L2)
__device__ __half g_xh[(size_t)MAXN * C_DIM]; // x in fp16
__device__ __half g_wh[C_DIM * HC];           // W in fp16
__device__ float g_asrc[MAXN * H_DIM];
__device__ float g_adst[MAXN * H_DIM];
__device__ int   g_deg[MAXN];
__device__ int   g_off[MAXN];
__device__ int   g_cur[MAXN];
__device__ int   g_bsum[64];
__device__ int   g_ssrc[MAXE];                // edge src ids grouped by dst

// ---------------- helpers ----------------
__device__ __forceinline__ float lrelu(float v) {
    return v > 0.f ? v : NEG_SLOPE * v;
}
__device__ __forceinline__ unsigned fenc(float f) {
    unsigned u = __float_as_uint(f);
    return (u & 0x80000000u) ? ~u : (u | 0x80000000u);
}
__device__ __forceinline__ float fdec(unsigned e) {
    return (e & 0x80000000u) ? __uint_as_float(e & 0x7FFFFFFFu)
                             : __uint_as_float(~e);
}

// ---------------- converts: fp32 -> fp16 ----------------
__global__ void convert_x(const float* __restrict__ x, int n4) {
    int i = blockIdx.x * blockDim.x + threadIdx.x;
    if (i < n4) {
        float4 v = reinterpret_cast<const float4*>(x)[i];
        __half2 h[2];
        h[0] = __floats2half2_rn(v.x, v.y);
        h[1] = __floats2half2_rn(v.z, v.w);
        reinterpret_cast<uint2*>(g_xh)[i] = *reinterpret_cast<uint2*>(h);
    }
}
__global__ void convert_w(const float* __restrict__ W, int n4) {
    int i = blockIdx.x * blockDim.x + threadIdx.x;
    if (i < n4) {
        float4 v = reinterpret_cast<const float4*>(W)[i];
        __half2 h[2];
        h[0] = __floats2half2_rn(v.x, v.y);
        h[1] = __floats2half2_rn(v.z, v.w);
        reinterpret_cast<uint2*>(g_wh)[i] = *reinterpret_cast<uint2*>(h);
    }
}

// ---------------- K1: tensor-core GEMM h = x @ W + fused logit epilogue ----------
// grid = (H, ceil(N/64)), block = 128 (4 warps). Block (head, rowblk) computes
// h[row0:row0+64, head, 0:64] via wmma m16n16k16 (fp16 in, fp32 accum).
#define LDH 72   // half padding (144B rows, 16B-aligned, ldm mult of 8)
#define LDC 72   // float padding for C tile

__global__ __launch_bounds__(128) void gemm_wmma(
    const float* __restrict__ att_src, const float* __restrict__ att_dst, int N)
{
    __shared__ __half Ah[64 * LDH];
    __shared__ __half Bh[64 * LDH];
    __shared__ float  Cs[64 * LDC];
    __shared__ float  att_s[64], att_d[64];

    const int head = blockIdx.x;
    const int row0 = blockIdx.y * 64;
    const int tid  = threadIdx.x;
    const int warp = tid >> 5;

    if (tid < 64) {
        att_s[tid] = att_src[head * 64 + tid];
        att_d[tid] = att_dst[head * 64 + tid];
    }
    // load A tile (64 rows x 64 halfs = 8 int4/row)
    for (int i = tid; i < 512; i += 128) {
        int r = i >> 3, seg = i & 7;
        int gr = row0 + r;
        int4 v;
        if (gr < N) v = *reinterpret_cast<const int4*>(g_xh + (size_t)gr * 64 + seg * 8);
        else        v = make_int4(0, 0, 0, 0);
        *reinterpret_cast<int4*>(&Ah[r * LDH + seg * 8]) = v;
    }
    // load B tile: W[k][head*64 + c]
    for (int i = tid; i < 512; i += 128) {
        int k = i >> 3, seg = i & 7;
        *reinterpret_cast<int4*>(&Bh[k * LDH + seg * 8]) =
            *reinterpret_cast<const int4*>(g_wh + k * HC + head * 64 + seg * 8);
    }
    __syncthreads();

    // each warp: 16-row strip x 64 cols
    wmma::fragment<wmma::accumulator, 16, 16, 16, float> acc[4];
#pragma unroll
    for (int c = 0; c < 4; ++c) wmma::fill_fragment(acc[c], 0.f);
#pragma unroll
    for (int k = 0; k < 4; ++k) {
        wmma::fragment<wmma::matrix_a, 16, 16, 16, __half, wmma::row_major> a;
        wmma::load_matrix_sync(a, &Ah[warp * 16 * LDH + k * 16], LDH);
#pragma unroll
        for (int c = 0; c < 4; ++c) {
            wmma::fragment<wmma::matrix_b, 16, 16, 16, __half, wmma::row_major> b;
            wmma::load_matrix_sync(b, &Bh[k * 16 * LDH + c * 16], LDH);
            wmma::mma_sync(acc[c], a, b, acc[c]);
        }
    }
#pragma unroll
    for (int c = 0; c < 4; ++c)
        wmma::store_matrix_sync(&Cs[warp * 16 * LDC + c * 16], acc[c], LDC, wmma::mem_row_major);
    __syncthreads();

    // epilogue: 2 threads per row (each 32 cols)
    const int r  = tid >> 1;
    const int hs = tid & 1;
    const int gr = row0 + r;
    float ps = 0.f, pd = 0.f;
    const float* crow = &Cs[r * LDC + hs * 32];
#pragma unroll
    for (int j = 0; j < 32; ++j) {
        float v = crow[j];
        ps = fmaf(v, att_s[hs * 32 + j], ps);
        pd = fmaf(v, att_d[hs * 32 + j], pd);
    }
    ps += __shfl_xor_sync(0xffffffffu, ps, 1);
    pd += __shfl_xor_sync(0xffffffffu, pd, 1);
    if (hs == 0 && gr < N) {
        g_asrc[gr * H_DIM + head] = ps;
        g_adst[gr * H_DIM + head] = pd;
    }
    // h store: this thread writes 32 halfs of its row (4x int4)
    if (gr < N) {
#pragma unroll
        for (int s = 0; s < 4; ++s) {
            int c = hs * 32 + s * 8;
            __half2 hh[4];
            hh[0] = __floats2half2_rn(Cs[r * LDC + c],     Cs[r * LDC + c + 1]);
            hh[1] = __floats2half2_rn(Cs[r * LDC + c + 2], Cs[r * LDC + c + 3]);
            hh[2] = __floats2half2_rn(Cs[r * LDC + c + 4], Cs[r * LDC + c + 5]);
            hh[3] = __floats2half2_rn(Cs[r * LDC + c + 6], Cs[r * LDC + c + 7]);
            *reinterpret_cast<int4*>(g_hh + (size_t)gr * HC + head * 64 + c) =
                *reinterpret_cast<int4*>(hh);
        }
    }
}

// ---------------- CSR build ----------------
__global__ void zero_deg(int N) {
    int i = blockIdx.x * blockDim.x + threadIdx.x;
    if (i < N) g_deg[i] = 0;
}
__global__ void hist_kernel(const int* __restrict__ dst, int E) {
    for (int e = blockIdx.x * blockDim.x + threadIdx.x; e < E;
         e += gridDim.x * blockDim.x)
        atomicAdd(&g_deg[dst[e]], 1);
}
__global__ __launch_bounds__(1024) void scan_block(int N) {
    __shared__ int sm[1024];
    int t = threadIdx.x;
    int i = blockIdx.x * 1024 + t;
    sm[t] = (i < N) ? g_deg[i] : 0;
    __syncthreads();
#pragma unroll
    for (int ofs = 1; ofs < 1024; ofs <<= 1) {
        int add = (t >= ofs) ? sm[t - ofs] : 0;
        __syncthreads();
        sm[t] += add;
        __syncthreads();
    }
    if (i < N) g_off[i] = sm[t];                 // inclusive (temp)
    if (t == 1023) g_bsum[blockIdx.x] = sm[1023];
}
__global__ __launch_bounds__(1024) void scan_bsum(int nb) {
    __shared__ int sm[1024];
    int t = threadIdx.x;
    int orig = (t < nb) ? g_bsum[t] : 0;
    sm[t] = orig;
    __syncthreads();
#pragma unroll
    for (int ofs = 1; ofs < 1024; ofs <<= 1) {
        int add = (t >= ofs) ? sm[t - ofs] : 0;
        __syncthreads();
        sm[t] += add;
        __syncthreads();
    }
    if (t < nb) g_bsum[t] = sm[t] - orig;        // exclusive block offsets
}
__global__ void finalize_off(int N) {
    int i = blockIdx.x * blockDim.x + threadIdx.x;
    if (i < N) {
        int ex = g_off[i] - g_deg[i] + g_bsum[i >> 10];
        g_off[i] = ex;
        g_cur[i] = ex;
    }
}
__global__ void scatter_kernel(const int* __restrict__ src, const int* __restrict__ dst, int E) {
    for (int e = blockIdx.x * blockDim.x + threadIdx.x; e < E;
         e += gridDim.x * blockDim.x) {
        int p = atomicAdd(&g_cur[dst[e]], 1);
        g_ssrc[p] = src[e];
    }
}

// ---------------- K6: per-node softmax + weighted aggregation ----------------
// one block (192 thr) per node; thread t owns features [4t, 4t+4) of the 768-wide
// h row (one LDG.64 = 2x half2 per edge); head of thread t is t>>4.
__global__ __launch_bounds__(192) void aggregate(
    const float* __restrict__ x, const float* __restrict__ bias,
    float* __restrict__ out, int N)
{
    const int n = blockIdx.x;
    const int t = threadIdx.x;
    const int head = t >> 4;

    __shared__ float    s_adst[H_DIM];
    __shared__ unsigned s_menc[H_DIM];
    __shared__ float    s_m[H_DIM];
    __shared__ float    s_sum[H_DIM];
    __shared__ float    s_w[64 * H_DIM];
    __shared__ int      s_src[64];
    __shared__ float    s_feat[HC];

    const int dg = g_deg[n];
    const int o  = g_off[n];

    if (t < H_DIM) { s_adst[t] = g_adst[n * H_DIM + t]; s_menc[t] = 0u; }
    __syncthreads();

    // ---- pass 1: per-head max (self loop + edges) ----
    if (t < H_DIM) {
        float al = lrelu(g_asrc[n * H_DIM + t] + s_adst[t]);
        atomicMax(&s_menc[t], fenc(al));
    }
    for (int base = 0; base < dg; base += 64) {
        int cnt = min(64, dg - base);
        if (t < cnt) s_src[t] = g_ssrc[o + base + t];
        __syncthreads();
        for (int idx = t; idx < cnt * H_DIM; idx += 192) {
            int e = idx / H_DIM, hh = idx - e * H_DIM;
            float al = lrelu(g_asrc[s_src[e] * H_DIM + hh] + s_adst[hh]);
            atomicMax(&s_menc[hh], fenc(al));
        }
        __syncthreads();
    }
    if (t < H_DIM) { s_m[t] = fdec(s_menc[t]); s_sum[t] = 0.f; }
    __syncthreads();

    // ---- self-loop contribution ----
    if (t < H_DIM) {
        float al = lrelu(g_asrc[n * H_DIM + t] + s_adst[t]);
        float w = __expf(al - s_m[t]);
        s_w[t]   = w;        // temp: self weights in s_w[0..11]
        s_sum[t] = w;
    }
    __syncthreads();
    float a0, a1, a2, a3;
    {
        float w = s_w[head];
        const __half2* hp = reinterpret_cast<const __half2*>(g_hh + (size_t)n * HC + t * 4);
        float2 f0 = __half22float2(hp[0]);
        float2 f1 = __half22float2(hp[1]);
        a0 = w * f0.x; a1 = w * f0.y; a2 = w * f1.x; a3 = w * f1.y;
    }
    __syncthreads();

    // ---- pass 2: exp-sum + weighted feature accumulation (64-edge chunks) ----
    for (int base = 0; base < dg; base += 64) {
        int cnt = min(64, dg - base);
        if (t < cnt) s_src[t] = g_ssrc[o + base + t];
        __syncthreads();
        for (int idx = t; idx < cnt * H_DIM; idx += 192) {
            int e = idx / H_DIM, hh = idx - e * H_DIM;
            float al = lrelu(g_asrc[s_src[e] * H_DIM + hh] + s_adst[hh]);
            float w = __expf(al - s_m[hh]);
            s_w[idx] = w;
            atomicAdd(&s_sum[hh], w);
        }
        __syncthreads();

        int e = 0;
        for (; e + 4 <= cnt; e += 4) {
            const __half2* p0 = reinterpret_cast<const __half2*>(g_hh + (size_t)s_src[e]     * HC + t * 4);
            const __half2* p1 = reinterpret_cast<const __half2*>(g_hh + (size_t)s_src[e + 1] * HC + t * 4);
            const __half2* p2 = reinterpret_cast<const __half2*>(g_hh + (size_t)s_src[e + 2] * HC + t * 4);
            const __half2* p3 = reinterpret_cast<const __half2*>(g_hh + (size_t)s_src[e + 3] * HC + t * 4);
            __half2 h0a = p0[0], h0b = p0[1];
            __half2 h1a = p1[0], h1b = p1[1];
            __half2 h2a = p2[0], h2b = p2[1];
            __half2 h3a = p3[0], h3b = p3[1];
            float w0 = s_w[(e)     * H_DIM + head];
            float w1 = s_w[(e + 1) * H_DIM + head];
            float w2 = s_w[(e + 2) * H_DIM + head];
            float w3 = s_w[(e + 3) * H_DIM + head];
            float2 f;
            f = __half22float2(h0a); a0 = fmaf(w0, f.x, a0); a1 = fmaf(w0, f.y, a1);
            f = __half22float2(h0b); a2 = fmaf(w0, f.x, a2); a3 = fmaf(w0, f.y, a3);
            f = __half22float2(h1a); a0 = fmaf(w1, f.x, a0); a1 = fmaf(w1, f.y, a1);
            f = __half22float2(h1b); a2 = fmaf(w1, f.x, a2); a3 = fmaf(w1, f.y, a3);
            f = __half22float2(h2a); a0 = fmaf(w2, f.x, a0); a1 = fmaf(w2, f.y, a1);
            f = __half22float2(h2b); a2 = fmaf(w2, f.x, a2); a3 = fmaf(w2, f.y, a3);
            f = __half22float2(h3a); a0 = fmaf(w3, f.x, a0); a1 = fmaf(w3, f.y, a1);
            f = __half22float2(h3b); a2 = fmaf(w3, f.x, a2); a3 = fmaf(w3, f.y, a3);
        }
        for (; e < cnt; ++e) {
            const __half2* p = reinterpret_cast<const __half2*>(g_hh + (size_t)s_src[e] * HC + t * 4);
            __half2 ha = p[0], hb = p[1];
            float w = s_w[e * H_DIM + head];
            float2 f;
            f = __half22float2(ha); a0 = fmaf(w, f.x, a0); a1 = fmaf(w, f.y, a1);
            f = __half22float2(hb); a2 = fmaf(w, f.x, a2); a3 = fmaf(w, f.y, a3);
        }
        __syncthreads();
    }

    // ---- normalize per head, head-mean, residual, relu ----
    {
        float inv = 1.f / (s_sum[head] + EPS_DEN);
        float4 v = make_float4(a0 * inv, a1 * inv, a2 * inv, a3 * inv);
        *reinterpret_cast<float4*>(&s_feat[t * 4]) = v;
    }
    __syncthreads();
    if (t < 64) {
        float v = 0.f;
#pragma unroll
        for (int h = 0; h < H_DIM; ++h) v += s_feat[h * 64 + t];
        v = v * (1.f / (float)H_DIM) + bias[t] + x[(size_t)n * 64 + t];
        out[(size_t)n * 64 + t] = fmaxf(v, 0.f);
    }
}

// ---------------- launch ----------------
extern "C" void kernel_launch(void* const* d_in, const int* in_sizes, int n_in,
                              void* d_out, int out_size)
{
    (void)n_in; (void)out_size;
    const float* x     = (const float*)d_in[0];
    const int*   ei    = (const int*)  d_in[1];
    const float* W     = (const float*)d_in[2];
    const float* att_s = (const float*)d_in[3];
    const float* att_d = (const float*)d_in[4];
    const float* bias  = (const float*)d_in[5];
    float* out = (float*)d_out;

    const int N = in_sizes[0] / C_DIM;
    const int E = in_sizes[1] / 2;
    const int* src = ei;
    const int* dst = ei + E;

    int xn4 = (N * C_DIM) / 4;
    int wn4 = (C_DIM * HC) / 4;
    convert_x<<<(xn4 + 255) / 256, 256>>>(x, xn4);
    convert_w<<<(wn4 + 255) / 256, 256>>>(W, wn4);
    zero_deg<<<(N + 255) / 256, 256>>>(N);

    // 4th launch: ncu capture lands here
    gemm_wmma<<<dim3(H_DIM, (N + 63) / 64), 128>>>(att_s, att_d, N);

    hist_kernel<<<592, 256>>>(dst, E);
    int nb = (N + 1023) / 1024;
    scan_block<<<nb, 1024>>>(N);
    scan_bsum<<<1, 1024>>>(nb);
    finalize_off<<<(N + 255) / 256, 256>>>(N);
    scatter_kernel<<<592, 256>>>(src, dst, E);

    aggregate<<<N, 192>>>(x, bias, out, N);
}